// round 14
// baseline (speedup 1.0000x reference)
#include <cuda_runtime.h>
#include <cuda_bf16.h>

#define CDIM 128
#define NMAX 50000
#define EMAX 640000

// ---------------- scratch ----------------
__device__ __align__(16) float g_deg[NMAX];
__device__ __align__(16) float g_s[NMAX * CDIM];        // pass1 sums; reused as attn acc
__device__ __align__(16) float g_KV[NMAX * 2 * CDIM];   // [m][0:128]=K, [m][128:256]=V
__device__ __align__(16) float g_Q[NMAX * CDIM];
__device__ __align__(16) __nv_bfloat16 g_WcH[256 * 256]; // folded KV weights [n(256)][k(256)]
__device__ __align__(16) __nv_bfloat16 g_WcL[256 * 256];
__device__ __align__(16) __nv_bfloat16 g_WqH[128 * 128];
__device__ __align__(16) __nv_bfloat16 g_WqL[128 * 128];
__device__ __align__(16) float g_bc0[256];
__device__ __align__(16) float g_bc1[256];
__device__ __align__(16) float g_lm[NMAX];
__device__ __align__(16) float g_Zd[NMAX];
// CSR (edge list 2 only, keyed by dst)
__device__ int g_cnt2[NMAX];
__device__ int g_off2[NMAX + 1];
__device__ int g_pos2[NMAX];
__device__ int g_csr2m[EMAX];
__device__ unsigned g_maxbits;
__device__ float g_Z;
__device__ int g_idx64;

__device__ __forceinline__ int ld_idx(const void* p, size_t e) {
    if (g_idx64) return (int)((const long long*)p)[e];
    return ((const int*)p)[e];
}
__device__ __forceinline__ void red_add_v4(float* p, float4 v) {
    asm volatile("red.global.add.v4.f32 [%0], {%1, %2, %3, %4};"
                 :: "l"(p), "f"(v.x), "f"(v.y), "f"(v.z), "f"(v.w) : "memory");
}
__device__ __forceinline__ unsigned flipf(float f) {
    unsigned u = __float_as_uint(f);
    return (u & 0x80000000u) ? ~u : (u | 0x80000000u);
}
__device__ __forceinline__ float unflipf(unsigned u) {
    return __uint_as_float((u & 0x80000000u) ? (u ^ 0x80000000u) : ~u);
}
__device__ __forceinline__ unsigned pack_bf2(float x, float y) {
    __nv_bfloat162 h = __floats2bfloat162_rn(x, y);
    return *(unsigned*)&h;
}

// ---------------- detect index dtype ----------------
__global__ void k_detect(const int* __restrict__ ei1w) {
    int v = ei1w[2 * threadIdx.x + 1];
    unsigned any = __ballot_sync(0xffffffffu, v != 0);
    __shared__ int nz[16];
    if ((threadIdx.x & 31) == 0) nz[threadIdx.x >> 5] = (any != 0);
    __syncthreads();
    if (threadIdx.x == 0) {
        int a = 0;
        for (int r = 0; r < (int)(blockDim.x >> 5); r++) a |= nz[r];
        g_idx64 = !a;
    }
}

// ---------------- zero: g_s, g_deg, cnt2, scalars ----------------
__global__ void k_zero(int nmid) {
    int i = blockIdx.x * blockDim.x + threadIdx.x;
    int stride = gridDim.x * blockDim.x;
    float4 z = make_float4(0.f, 0.f, 0.f, 0.f);
    for (int t = i; t < nmid * CDIM / 4; t += stride) ((float4*)g_s)[t] = z;
    for (int t = i; t < nmid; t += stride) { g_deg[t] = 0.f; g_cnt2[t] = 0; }
    if (i == 0) { g_maxbits = 0u; g_Z = 0.f; }
}

// ---------------- deg count (edge-parallel; overlaps scatter1) ----------------
__global__ void k_deg(const void* __restrict__ ei1, int E1, int nmid) {
    int e = blockIdx.x * blockDim.x + threadIdx.x;
    if (e >= E1) return;
    int mid = ld_idx(ei1, (size_t)E1 + e);
    if ((unsigned)mid < (unsigned)nmid) atomicAdd(&g_deg[mid], 1.0f);
}

// ---------------- fold weights ----------------
__global__ void k_fold(const float* __restrict__ W1w, const float* __restrict__ W2w,
                       const float* __restrict__ W1b, const float* __restrict__ W2b,
                       const float* __restrict__ qw,
                       const float* __restrict__ kw, const float* __restrict__ vw,
                       const float* __restrict__ kb, const float* __restrict__ vb) {
    int idx = blockIdx.x * blockDim.x + threadIdx.x;
    if (idx < 65536) {
        int i = idx >> 8, j = idx & 255;
        const float* Wa = (j < 128) ? kw : vw;
        int jj = j & 127;
        const float* Wx = (i < 128) ? W1w : W2w;
        int ii = i & 127;
        float acc = 0.f;
        #pragma unroll 8
        for (int t = 0; t < 128; t++) acc += Wa[jj * 128 + t] * Wx[t * 128 + ii];
        __nv_bfloat16 h = __float2bfloat16(acc);
        g_WcH[j * 256 + i] = h;
        g_WcL[j * 256 + i] = __float2bfloat16(acc - __bfloat162float(h));
    } else if (idx < 65536 + 16384) {
        int t2 = idx - 65536;
        float a = qw[t2];
        __nv_bfloat16 h = __float2bfloat16(a);
        g_WqH[t2] = h;
        g_WqL[t2] = __float2bfloat16(a - __bfloat162float(h));
    } else if (idx < 65536 + 16384 + 256) {
        int j = idx - (65536 + 16384);
        const float* Wa = (j < 128) ? kw : vw;
        int jj = j & 127;
        float acc = 0.f;
        for (int t = 0; t < 128; t++) acc += Wa[jj * 128 + t] * (W1b[t] + W2b[t]);
        g_bc1[j] = acc;
        g_bc0[j] = (j < 128) ? kb[jj] : vb[jj];
    }
}

// ---------------- edge pass 1 (atomic scatter; deg moved to k_deg) ----------------
__global__ void k_scatter1(const float* __restrict__ xsrc, const void* __restrict__ ei1, int E1) {
    int warp = (blockIdx.x * blockDim.x + threadIdx.x) >> 5;
    int lane = threadIdx.x & 31;
    if (warp >= E1) return;
    int src = ld_idx(ei1, warp);
    int mid = ld_idx(ei1, (size_t)E1 + warp);
    float4 v = *(const float4*)(xsrc + (size_t)src * CDIM + lane * 4);
    red_add_v4(g_s + (size_t)mid * CDIM + lane * 4, v);
}

// ---------------- CSR2: count / scan / fill ----------------
__global__ void k_count2(const void* __restrict__ ei2, int E2, int nmid) {
    int e = blockIdx.x * blockDim.x + threadIdx.x;
    if (e >= E2) return;
    int mid = ld_idx(ei2, e);
    int dst = ld_idx(ei2, (size_t)E2 + e);
    if ((unsigned)mid < (unsigned)nmid && (unsigned)dst < (unsigned)nmid)
        atomicAdd(&g_cnt2[dst], 1);
}

__global__ void k_scan(int n) {
    __shared__ int ps[1024];
    int tid = threadIdx.x;
    int chunk = (n + 1023) >> 10;
    int lo = tid * chunk;
    if (lo > n) lo = n;
    int hi = lo + chunk;
    if (hi > n) hi = n;
    int s = 0;
    for (int i = lo; i < hi; i++) s += g_cnt2[i];
    ps[tid] = s;
    __syncthreads();
    for (int o = 1; o < 1024; o <<= 1) {
        int v = (tid >= o) ? ps[tid - o] : 0;
        __syncthreads();
        ps[tid] += v;
        __syncthreads();
    }
    int base = (tid > 0) ? ps[tid - 1] : 0;
    for (int i = lo; i < hi; i++) {
        g_off2[i] = base;
        g_pos2[i] = base;
        base += g_cnt2[i];
    }
    if (tid == 0) g_off2[n] = ps[1023];
}

__global__ void k_fill2(const void* __restrict__ ei2, int E2, int nmid) {
    int e = blockIdx.x * blockDim.x + threadIdx.x;
    if (e >= E2) return;
    int mid = ld_idx(ei2, e);
    int dst = ld_idx(ei2, (size_t)E2 + e);
    if ((unsigned)mid < (unsigned)nmid && (unsigned)dst < (unsigned)nmid) {
        int p = atomicAdd(&g_pos2[dst], 1);
        if ((unsigned)p < (unsigned)EMAX) g_csr2m[p] = mid;
    }
}

// ---------------- tensor-core GEMMs (bf16 3-term split), all K=128 ----------------
// MODE 0 (Q):   g_Q[m][n]  = x_dst[m] @ Wq[n]ᵀ + qb[n]                 (NLD=128)
// MODE 1 (KVa): g_KV[m][n] = deg[m]·x_mid[m] @ Wc[n][0:128]ᵀ + bc0[n] + deg[m]·bc1[n]
// MODE 2 (KVb): g_KV[m][n] += g_s[m] @ Wc[n][128:256]ᵀ   (X arg ignored; reads g_s in device code)
#define ASTR 24
template <int MODE>
__global__ void __launch_bounds__(256, 2) k_gemm_tc(const float* __restrict__ X,
                                                    const float* __restrict__ qb, int M) {
    const int NLD = (MODE == 0) ? 128 : 256;
    const int BSTR = (MODE == 0) ? 128 : 256;
    const int KOFF = (MODE == 2) ? 128 : 0;
    float* out = (MODE == 0) ? g_Q : g_KV;
    const __nv_bfloat16* BHg = (MODE == 0) ? g_WqH : g_WcH;
    const __nv_bfloat16* BLg = (MODE == 0) ? g_WqL : g_WcL;
    const float* Xe = (MODE == 2) ? (const float*)g_s : X;   // device-side symbol ref (legal here)

    __shared__ __align__(16) unsigned short Ah[128 * ASTR];
    __shared__ __align__(16) unsigned short Al[128 * ASTR];
    __shared__ __align__(16) unsigned short Bh[128 * ASTR];
    __shared__ __align__(16) unsigned short Bl[128 * ASTR];
    __shared__ float degS[128], b0s[128], b1s[128];

    int tid = threadIdx.x;
    int m0 = blockIdx.x * 128, n0 = blockIdx.y * 128;

    if (tid < 128) {
        int m = m0 + tid;
        if (MODE == 1) {
            degS[tid] = (m < M) ? g_deg[m] : 0.f;
            b0s[tid] = g_bc0[n0 + tid];
            b1s[tid] = g_bc1[n0 + tid];
        } else if (MODE == 0) {
            b0s[tid] = qb[tid];
        }
    }
    __syncthreads();

    int lane = tid & 31, wid = tid >> 5;
    int g = lane >> 2, t = lane & 3;
    int wm = (wid >> 2) * 64, wn = (wid & 3) * 32;

    float acc[4][4][4];
    #pragma unroll
    for (int mt = 0; mt < 4; mt++)
        #pragma unroll
        for (int nt = 0; nt < 4; nt++)
            #pragma unroll
            for (int r = 0; r < 4; r++) acc[mt][nt][r] = 0.f;

    int m_r = tid >> 1;
    int khalf = (tid & 1) * 8;

    for (int kt = 0; kt < 8; kt++) {
        int kg = kt * 16 + khalf;
        float f[8];
        {
            int m = m0 + m_r;
            if (m < M) {
                const float* src = Xe + (size_t)m * 128 + kg;
                float d = (MODE == 1) ? degS[m_r] : 1.f;
                float4 v0 = *(const float4*)src;
                float4 v1 = *(const float4*)(src + 4);
                f[0] = v0.x * d; f[1] = v0.y * d; f[2] = v0.z * d; f[3] = v0.w * d;
                f[4] = v1.x * d; f[5] = v1.y * d; f[6] = v1.z * d; f[7] = v1.w * d;
            } else {
                #pragma unroll
                for (int j = 0; j < 8; j++) f[j] = 0.f;
            }
        }
        unsigned hi[4], lo[4];
        #pragma unroll
        for (int j = 0; j < 4; j++) {
            __nv_bfloat162 h2 = __floats2bfloat162_rn(f[2 * j], f[2 * j + 1]);
            hi[j] = *(unsigned*)&h2;
            float r0 = f[2 * j]     - __bfloat162float(h2.x);
            float r1 = f[2 * j + 1] - __bfloat162float(h2.y);
            lo[j] = pack_bf2(r0, r1);
        }
        *(uint4*)&Ah[m_r * ASTR + khalf] = make_uint4(hi[0], hi[1], hi[2], hi[3]);
        *(uint4*)&Al[m_r * ASTR + khalf] = make_uint4(lo[0], lo[1], lo[2], lo[3]);
        size_t boff = (size_t)(n0 + m_r) * BSTR + KOFF + kg;
        *(uint4*)&Bh[m_r * ASTR + khalf] = *(const uint4*)(BHg + boff);
        *(uint4*)&Bl[m_r * ASTR + khalf] = *(const uint4*)(BLg + boff);
        __syncthreads();

        #pragma unroll
        for (int term = 0; term < 3; term++) {
            const unsigned short* As = (term == 2) ? Al : Ah;
            const unsigned short* Bs = (term == 1) ? Bl : Bh;
            unsigned b[4][2];
            #pragma unroll
            for (int nt = 0; nt < 4; nt++) {
                int nb = (wn + nt * 8 + g) * ASTR + 2 * t;
                b[nt][0] = *(const unsigned*)&Bs[nb];
                b[nt][1] = *(const unsigned*)&Bs[nb + 8];
            }
            #pragma unroll
            for (int mt = 0; mt < 4; mt++) {
                int ra = (wm + mt * 16 + g) * ASTR + 2 * t;
                unsigned a0 = *(const unsigned*)&As[ra];
                unsigned a1 = *(const unsigned*)&As[ra + 8 * ASTR];
                unsigned a2 = *(const unsigned*)&As[ra + 8];
                unsigned a3 = *(const unsigned*)&As[ra + 8 * ASTR + 8];
                #pragma unroll
                for (int nt = 0; nt < 4; nt++) {
                    asm volatile(
                        "mma.sync.aligned.m16n8k16.row.col.f32.bf16.bf16.f32 "
                        "{%0,%1,%2,%3}, {%4,%5,%6,%7}, {%8,%9}, {%0,%1,%2,%3};"
                        : "+f"(acc[mt][nt][0]), "+f"(acc[mt][nt][1]),
                          "+f"(acc[mt][nt][2]), "+f"(acc[mt][nt][3])
                        : "r"(a0), "r"(a1), "r"(a2), "r"(a3),
                          "r"(b[nt][0]), "r"(b[nt][1]));
                }
            }
        }
        __syncthreads();
    }

    #pragma unroll
    for (int mt = 0; mt < 4; mt++) {
        int r0l = wm + mt * 16 + g;
        int r1l = r0l + 8;
        int mA = m0 + r0l, mB = m0 + r1l;
        float dA = (MODE == 1) ? degS[r0l] : 0.f;
        float dB = (MODE == 1) ? degS[r1l] : 0.f;
        #pragma unroll
        for (int nt = 0; nt < 4; nt++) {
            int cl = wn + nt * 8 + 2 * t;
            if (mA < M) {
                float* p = out + (size_t)mA * NLD + n0 + cl;
                float2 o;
                if (MODE == 2) {
                    float2 prev = *(float2*)p;
                    o = make_float2(prev.x + acc[mt][nt][0], prev.y + acc[mt][nt][1]);
                } else if (MODE == 1) {
                    o = make_float2(acc[mt][nt][0] + b0s[cl] + dA * b1s[cl],
                                    acc[mt][nt][1] + b0s[cl + 1] + dA * b1s[cl + 1]);
                } else {
                    o = make_float2(acc[mt][nt][0] + b0s[cl], acc[mt][nt][1] + b0s[cl + 1]);
                }
                *(float2*)p = o;
            }
            if (mB < M) {
                float* p = out + (size_t)mB * NLD + n0 + cl;
                float2 o;
                if (MODE == 2) {
                    float2 prev = *(float2*)p;
                    o = make_float2(prev.x + acc[mt][nt][2], prev.y + acc[mt][nt][3]);
                } else if (MODE == 1) {
                    o = make_float2(acc[mt][nt][2] + b0s[cl] + dB * b1s[cl],
                                    acc[mt][nt][3] + b0s[cl + 1] + dB * b1s[cl + 1]);
                } else {
                    o = make_float2(acc[mt][nt][2] + b0s[cl], acc[mt][nt][3] + b0s[cl + 1]);
                }
                *(float2*)p = o;
            }
        }
    }
}

// ---------------- fused attention pass (warp-per-dst, online softmax, 2-edge) ----------------
__global__ void k_attn(int ndst, int E2) {
    __shared__ float wmx[8];
    int warp = (blockIdx.x * blockDim.x + threadIdx.x) >> 5;
    int lane = threadIdx.x & 31;
    int wid = threadIdx.x >> 5;
    float lm = -3.4e38f;
    if (warp < ndst) {
        float4 q = *(const float4*)(g_Q + (size_t)warp * CDIM + lane * 4);
        int b = g_off2[warp], e = g_off2[warp + 1];
        if (b < 0) b = 0;
        if (e > E2) e = E2;
        float Zd = 0.f;
        float4 acc = make_float4(0.f, 0.f, 0.f, 0.f);
        int j = b;
        for (; j + 1 < e; j += 2) {
            unsigned m0 = (unsigned)g_csr2m[j], m1 = (unsigned)g_csr2m[j + 1];
            if (m0 >= NMAX) m0 = 0;
            if (m1 >= NMAX) m1 = 0;
            const float* r0 = g_KV + (size_t)m0 * 2 * CDIM;
            const float* r1 = g_KV + (size_t)m1 * 2 * CDIM;
            float4 k0 = *(const float4*)(r0 + lane * 4);
            float4 k1 = *(const float4*)(r1 + lane * 4);
            float4 v0 = *(const float4*)(r0 + CDIM + lane * 4);
            float4 v1 = *(const float4*)(r1 + CDIM + lane * 4);
            float d0 = k0.x * q.x + k0.y * q.y + k0.z * q.z + k0.w * q.w;
            float d1 = k1.x * q.x + k1.y * q.y + k1.z * q.z + k1.w * q.w;
            #pragma unroll
            for (int o = 16; o > 0; o >>= 1) {
                d0 += __shfl_xor_sync(0xffffffffu, d0, o);
                d1 += __shfl_xor_sync(0xffffffffu, d1, o);
            }
            float s0 = d0 * 0.08838834764831845f;
            float s1 = d1 * 0.08838834764831845f;
            float nm = fmaxf(lm, fmaxf(s0, s1));
            float sc = __expf(lm - nm);
            float w0 = __expf(s0 - nm);
            float w1 = __expf(s1 - nm);
            Zd = Zd * sc + w0 + w1;
            acc.x = acc.x * sc + w0 * v0.x + w1 * v1.x;
            acc.y = acc.y * sc + w0 * v0.y + w1 * v1.y;
            acc.z = acc.z * sc + w0 * v0.z + w1 * v1.z;
            acc.w = acc.w * sc + w0 * v0.w + w1 * v1.w;
            lm = nm;
        }
        if (j < e) {
            unsigned m0 = (unsigned)g_csr2m[j];
            if (m0 >= NMAX) m0 = 0;
            const float* r0 = g_KV + (size_t)m0 * 2 * CDIM;
            float4 k0 = *(const float4*)(r0 + lane * 4);
            float4 v0 = *(const float4*)(r0 + CDIM + lane * 4);
            float d0 = k0.x * q.x + k0.y * q.y + k0.z * q.z + k0.w * q.w;
            #pragma unroll
            for (int o = 16; o > 0; o >>= 1) d0 += __shfl_xor_sync(0xffffffffu, d0, o);
            float s0 = d0 * 0.08838834764831845f;
            float nm = fmaxf(lm, s0);
            float sc = __expf(lm - nm);
            float w0 = __expf(s0 - nm);
            Zd = Zd * sc + w0;
            acc.x = acc.x * sc + w0 * v0.x;
            acc.y = acc.y * sc + w0 * v0.y;
            acc.z = acc.z * sc + w0 * v0.z;
            acc.w = acc.w * sc + w0 * v0.w;
            lm = nm;
        }
        *(float4*)(g_s + (size_t)warp * CDIM + lane * 4) = acc;
        if (lane == 0) { g_lm[warp] = lm; g_Zd[warp] = Zd; }
    }
    if (lane == 0) wmx[wid] = lm;
    __syncthreads();
    if (threadIdx.x == 0) {
        float m = wmx[0];
        #pragma unroll
        for (int r = 1; r < 8; r++) m = fmaxf(m, wmx[r]);
        atomicMax(&g_maxbits, flipf(m));
    }
}

// ---------------- Z = sum_d Zd * exp(lm_d - gm) ----------------
__global__ void k_zZ(int ndst) {
    __shared__ float wm[8];
    float gm = unflipf(g_maxbits);
    float loc = 0.f;
    int i = blockIdx.x * blockDim.x + threadIdx.x;
    int stride = gridDim.x * blockDim.x;
    for (int t = i; t < ndst; t += stride)
        loc += g_Zd[t] * __expf(g_lm[t] - gm);
    #pragma unroll
    for (int o = 16; o > 0; o >>= 1) loc += __shfl_xor_sync(0xffffffffu, loc, o);
    if ((threadIdx.x & 31) == 0) wm[threadIdx.x >> 5] = loc;
    __syncthreads();
    if (threadIdx.x == 0) {
        float bsum = 0.f;
        #pragma unroll
        for (int r = 0; r < 8; r++) bsum += wm[r];
        atomicAdd(&g_Z, bsum);
    }
}

// ---------------- final: out[d] = acc_d * exp(lm_d - gm) / Z ----------------
__global__ void k_final(float* __restrict__ out, int ndst) {
    int i = blockIdx.x * blockDim.x + threadIdx.x;
    int total = ndst * (CDIM / 4);
    if (i >= total) return;
    int d = i >> 5;
    float gm = unflipf(g_maxbits);
    float w = __expf(g_lm[d] - gm) / g_Z;
    float4 a = ((const float4*)g_s)[i];
    float4 o = make_float4(a.x * w, a.y * w, a.z * w, a.w * w);
    ((float4*)out)[i] = o;
}

// ---------------- stream/event pool ----------
namespace {
struct StreamPool {
    cudaStream_t s1 = nullptr, s2 = nullptr;
    cudaEvent_t eS = nullptr, eDZ = nullptr, e1 = nullptr, e2 = nullptr, eDeg = nullptr;
    bool ok = false;
    StreamPool() {
        ok = (cudaStreamCreateWithFlags(&s1, cudaStreamNonBlocking) == cudaSuccess) &&
             (cudaStreamCreateWithFlags(&s2, cudaStreamNonBlocking) == cudaSuccess) &&
             (cudaEventCreateWithFlags(&eS,   cudaEventDisableTiming) == cudaSuccess) &&
             (cudaEventCreateWithFlags(&eDZ,  cudaEventDisableTiming) == cudaSuccess) &&
             (cudaEventCreateWithFlags(&e1,   cudaEventDisableTiming) == cudaSuccess) &&
             (cudaEventCreateWithFlags(&e2,   cudaEventDisableTiming) == cudaSuccess) &&
             (cudaEventCreateWithFlags(&eDeg, cudaEventDisableTiming) == cudaSuccess);
    }
};
StreamPool g_sp;
}

// ---------------- launch ----------------
extern "C" void kernel_launch(void* const* d_in, const int* in_sizes, int n_in,
                              void* d_out, int out_size) {
    const float* x_src = (const float*)d_in[0];
    const float* x_mid = (const float*)d_in[1];
    const float* x_dst = (const float*)d_in[2];
    const void* ei1 = d_in[3];
    const void* ei2 = d_in[4];
    const float* W1w = (const float*)d_in[5];
    const float* W1b = (const float*)d_in[6];
    const float* W2w = (const float*)d_in[7];
    const float* W2b = (const float*)d_in[8];
    const float* qw  = (const float*)d_in[9];
    const float* qb  = (const float*)d_in[10];
    const float* kw  = (const float*)d_in[11];
    const float* kb  = (const float*)d_in[12];
    const float* vw  = (const float*)d_in[13];
    const float* vb  = (const float*)d_in[14];
    float* out = (float*)d_out;

    int E1 = in_sizes[3] / 2;
    int E2 = in_sizes[4] / 2;
    int Nmid = in_sizes[1] / CDIM;
    int Ndst = in_sizes[2] / CDIM;

    dim3 gKV((Nmid + 127) / 128, 2);
    dim3 gQ((Ndst + 127) / 128, 1);
    int foldBlocks = (65536 + 16384 + 256 + 255) / 256;

    if (g_sp.ok) {
        // fork
        cudaEventRecord(g_sp.eS, 0);
        cudaStreamWaitEvent(g_sp.s1, g_sp.eS, 0);

        // track A (s1): detect -> zero -> scatter1
        k_detect<<<1, 512, 0, g_sp.s1>>>((const int*)ei1);
        k_zero<<<2048, 256, 0, g_sp.s1>>>(Nmid);
        cudaEventRecord(g_sp.eDZ, g_sp.s1);
        k_scatter1<<<(E1 + 7) / 8, 256, 0, g_sp.s1>>>(x_src, ei1, E1);
        cudaEventRecord(g_sp.e1, g_sp.s1);

        // track B (s2): deg count, then CSR build (needs detect+zero)
        cudaStreamWaitEvent(g_sp.s2, g_sp.eDZ, 0);
        k_deg<<<(E1 + 255) / 256, 256, 0, g_sp.s2>>>(ei1, E1, Nmid);
        cudaEventRecord(g_sp.eDeg, g_sp.s2);
        k_count2<<<(E2 + 255) / 256, 256, 0, g_sp.s2>>>(ei2, E2, Nmid);
        k_scan<<<1, 1024, 0, g_sp.s2>>>(Nmid);
        k_fill2<<<(E2 + 255) / 256, 256, 0, g_sp.s2>>>(ei2, E2, Nmid);
        cudaEventRecord(g_sp.e2, g_sp.s2);

        // track C (s0): fold -> Q GEMM -> (deg ready) KVa GEMM (overlaps scatter1)
        k_fold<<<foldBlocks, 256>>>(W1w, W2w, W1b, W2b, qw, kw, vw, kb, vb);
        k_gemm_tc<0><<<gQ, 256>>>(x_dst, qb, Ndst);
        cudaStreamWaitEvent(0, g_sp.eDeg, 0);
        k_gemm_tc<1><<<gKV, 256>>>(x_mid, nullptr, Nmid);
        // KVb needs scatter1's s + KVa (in-order on s0); reads g_s internally
        cudaStreamWaitEvent(0, g_sp.e1, 0);
        k_gemm_tc<2><<<gKV, 256>>>(nullptr, nullptr, Nmid);
        // attn needs CSR (e2) + GEMMs (in-order)
        cudaStreamWaitEvent(0, g_sp.e2, 0);
        k_attn<<<(Ndst + 7) / 8, 256>>>(Ndst, E2);
        k_zZ<<<256, 256>>>(Ndst);
        k_final<<<(Ndst * 32 + 255) / 256, 256>>>(out, Ndst);
    } else {
        // sequential fallback (identical math)
        k_detect<<<1, 512>>>((const int*)ei1);
        k_zero<<<2048, 256>>>(Nmid);
        k_fold<<<foldBlocks, 256>>>(W1w, W2w, W1b, W2b, qw, kw, vw, kb, vb);
        k_deg<<<(E1 + 255) / 256, 256>>>(ei1, E1, Nmid);
        k_scatter1<<<(E1 + 7) / 8, 256>>>(x_src, ei1, E1);
        k_count2<<<(E2 + 255) / 256, 256>>>(ei2, E2, Nmid);
        k_scan<<<1, 1024>>>(Nmid);
        k_fill2<<<(E2 + 255) / 256, 256>>>(ei2, E2, Nmid);
        k_gemm_tc<0><<<gQ, 256>>>(x_dst, qb, Ndst);
        k_gemm_tc<1><<<gKV, 256>>>(x_mid, nullptr, Nmid);
        k_gemm_tc<2><<<gKV, 256>>>(nullptr, nullptr, Nmid);
        k_attn<<<(Ndst + 7) / 8, 256>>>(Ndst, E2);
        k_zZ<<<256, 256>>>(Ndst);
        k_final<<<(Ndst * 32 + 255) / 256, 256>>>(out, Ndst);
    }
}

// round 15
// speedup vs baseline: 1.0859x; 1.0859x over previous
#include <cuda_runtime.h>
#include <cuda_bf16.h>

#define CDIM 128
#define NMAX 50000
#define EMAX 640000

// ---------------- scratch ----------------
__device__ __align__(16) float g_deg[NMAX];
__device__ __align__(16) float g_s[NMAX * CDIM];        // pass1 sums; reused as attn acc
__device__ __align__(16) float g_KV[NMAX * 2 * CDIM];   // [m][0:128]=K, [m][128:256]=V
__device__ __align__(16) float g_Q[NMAX * CDIM];
__device__ __align__(16) __nv_bfloat16 g_WcH[256 * 256];
__device__ __align__(16) __nv_bfloat16 g_WcL[256 * 256];
__device__ __align__(16) __nv_bfloat16 g_WqH[128 * 128];
__device__ __align__(16) __nv_bfloat16 g_WqL[128 * 128];
__device__ __align__(16) float g_bc0[256];
__device__ __align__(16) float g_bc1[256];
__device__ __align__(16) float g_lm[NMAX];
__device__ __align__(16) float g_Zd[NMAX];
// CSR (edge list 2 only, keyed by dst)
__device__ int g_cnt2[NMAX];
__device__ int g_off2[NMAX + 1];
__device__ int g_pos2[NMAX];
__device__ int g_csr2m[EMAX];
__device__ unsigned g_maxbits;
__device__ float g_Z;
__device__ int g_idx64;

__device__ __forceinline__ int ld_idx(const void* p, size_t e) {
    if (g_idx64) return (int)((const long long*)p)[e];
    return ((const int*)p)[e];
}
__device__ __forceinline__ void red_add_v4(float* p, float4 v) {
    asm volatile("red.global.add.v4.f32 [%0], {%1, %2, %3, %4};"
                 :: "l"(p), "f"(v.x), "f"(v.y), "f"(v.z), "f"(v.w) : "memory");
}
__device__ __forceinline__ unsigned flipf(float f) {
    unsigned u = __float_as_uint(f);
    return (u & 0x80000000u) ? ~u : (u | 0x80000000u);
}
__device__ __forceinline__ float unflipf(unsigned u) {
    return __uint_as_float((u & 0x80000000u) ? (u ^ 0x80000000u) : ~u);
}
__device__ __forceinline__ unsigned pack_bf2(float x, float y) {
    __nv_bfloat162 h = __floats2bfloat162_rn(x, y);
    return *(unsigned*)&h;
}

// ---------------- detect index dtype ----------------
__global__ void k_detect(const int* __restrict__ ei1w) {
    int v = ei1w[2 * threadIdx.x + 1];
    unsigned any = __ballot_sync(0xffffffffu, v != 0);
    __shared__ int nz[16];
    if ((threadIdx.x & 31) == 0) nz[threadIdx.x >> 5] = (any != 0);
    __syncthreads();
    if (threadIdx.x == 0) {
        int a = 0;
        for (int r = 0; r < (int)(blockDim.x >> 5); r++) a |= nz[r];
        g_idx64 = !a;
    }
}

// ---------------- zero: g_s, g_deg, cnt2, scalars ----------------
__global__ void k_zero(int nmid) {
    int i = blockIdx.x * blockDim.x + threadIdx.x;
    int stride = gridDim.x * blockDim.x;
    float4 z = make_float4(0.f, 0.f, 0.f, 0.f);
    for (int t = i; t < nmid * CDIM / 4; t += stride) ((float4*)g_s)[t] = z;
    for (int t = i; t < nmid; t += stride) { g_deg[t] = 0.f; g_cnt2[t] = 0; }
    if (i == 0) { g_maxbits = 0u; g_Z = 0.f; }
}

// ---------------- fold weights ----------------
__global__ void k_fold(const float* __restrict__ W1w, const float* __restrict__ W2w,
                       const float* __restrict__ W1b, const float* __restrict__ W2b,
                       const float* __restrict__ qw,
                       const float* __restrict__ kw, const float* __restrict__ vw,
                       const float* __restrict__ kb, const float* __restrict__ vb) {
    int idx = blockIdx.x * blockDim.x + threadIdx.x;
    if (idx < 65536) {
        int i = idx >> 8, j = idx & 255;
        const float* Wa = (j < 128) ? kw : vw;
        int jj = j & 127;
        const float* Wx = (i < 128) ? W1w : W2w;
        int ii = i & 127;
        float acc = 0.f;
        #pragma unroll 8
        for (int t = 0; t < 128; t++) acc += Wa[jj * 128 + t] * Wx[t * 128 + ii];
        __nv_bfloat16 h = __float2bfloat16(acc);
        g_WcH[j * 256 + i] = h;
        g_WcL[j * 256 + i] = __float2bfloat16(acc - __bfloat162float(h));
    } else if (idx < 65536 + 16384) {
        int t2 = idx - 65536;
        float a = qw[t2];
        __nv_bfloat16 h = __float2bfloat16(a);
        g_WqH[t2] = h;
        g_WqL[t2] = __float2bfloat16(a - __bfloat162float(h));
    } else if (idx < 65536 + 16384 + 256) {
        int j = idx - (65536 + 16384);
        const float* Wa = (j < 128) ? kw : vw;
        int jj = j & 127;
        float acc = 0.f;
        for (int t = 0; t < 128; t++) acc += Wa[jj * 128 + t] * (W1b[t] + W2b[t]);
        g_bc1[j] = acc;
        g_bc0[j] = (j < 128) ? kb[jj] : vb[jj];
    }
}

// ---------------- edge pass 1: 2 edges per warp, front-batched loads (MLP=2) ----------------
__global__ void k_scatter1(const float* __restrict__ xsrc, const void* __restrict__ ei1, int E1) {
    int warp = (blockIdx.x * blockDim.x + threadIdx.x) >> 5;
    int lane = threadIdx.x & 31;
    int e0 = warp * 2, e1 = warp * 2 + 1;
    if (e0 >= E1) return;
    bool has1 = (e1 < E1);
    int src0 = ld_idx(ei1, e0);
    int mid0 = ld_idx(ei1, (size_t)E1 + e0);
    int src1 = has1 ? ld_idx(ei1, e1) : src0;
    int mid1 = has1 ? ld_idx(ei1, (size_t)E1 + e1) : mid0;
    // two independent gathers issue back-to-back (LDG->LDG floor = 4 cyc)
    float4 v0 = *(const float4*)(xsrc + (size_t)src0 * CDIM + lane * 4);
    float4 v1 = *(const float4*)(xsrc + (size_t)src1 * CDIM + lane * 4);
    red_add_v4(g_s + (size_t)mid0 * CDIM + lane * 4, v0);
    if (has1) red_add_v4(g_s + (size_t)mid1 * CDIM + lane * 4, v1);
    if (lane == 0) {
        atomicAdd(&g_deg[mid0], 1.0f);
        if (has1) atomicAdd(&g_deg[mid1], 1.0f);
    }
}

// ---------------- CSR2: count / scan / fill ----------------
__global__ void k_count2(const void* __restrict__ ei2, int E2, int nmid) {
    int e = blockIdx.x * blockDim.x + threadIdx.x;
    if (e >= E2) return;
    int mid = ld_idx(ei2, e);
    int dst = ld_idx(ei2, (size_t)E2 + e);
    if ((unsigned)mid < (unsigned)nmid && (unsigned)dst < (unsigned)nmid)
        atomicAdd(&g_cnt2[dst], 1);
}

__global__ void k_scan(int n) {
    __shared__ int ps[1024];
    int tid = threadIdx.x;
    int chunk = (n + 1023) >> 10;
    int lo = tid * chunk;
    if (lo > n) lo = n;
    int hi = lo + chunk;
    if (hi > n) hi = n;
    int s = 0;
    for (int i = lo; i < hi; i++) s += g_cnt2[i];
    ps[tid] = s;
    __syncthreads();
    for (int o = 1; o < 1024; o <<= 1) {
        int v = (tid >= o) ? ps[tid - o] : 0;
        __syncthreads();
        ps[tid] += v;
        __syncthreads();
    }
    int base = (tid > 0) ? ps[tid - 1] : 0;
    for (int i = lo; i < hi; i++) {
        g_off2[i] = base;
        g_pos2[i] = base;
        base += g_cnt2[i];
    }
    if (tid == 0) g_off2[n] = ps[1023];
}

__global__ void k_fill2(const void* __restrict__ ei2, int E2, int nmid) {
    int e = blockIdx.x * blockDim.x + threadIdx.x;
    if (e >= E2) return;
    int mid = ld_idx(ei2, e);
    int dst = ld_idx(ei2, (size_t)E2 + e);
    if ((unsigned)mid < (unsigned)nmid && (unsigned)dst < (unsigned)nmid) {
        int p = atomicAdd(&g_pos2[dst], 1);
        if ((unsigned)p < (unsigned)EMAX) g_csr2m[p] = mid;
    }
}

// ---------------- tensor-core node GEMMs (bf16 3-term split) ----------------
#define ASTR 24
template <bool KVMODE>
__global__ void __launch_bounds__(256, 2) k_gemm_tc(const float* __restrict__ X,
                                                    const float* __restrict__ qb, int M) {
    const int KDIM = KVMODE ? 256 : 128;
    const int NLD  = KVMODE ? 256 : 128;
    float* out = KVMODE ? g_KV : g_Q;
    const __nv_bfloat16* BHg = KVMODE ? g_WcH : g_WqH;
    const __nv_bfloat16* BLg = KVMODE ? g_WcL : g_WqL;

    __shared__ __align__(16) unsigned short Ah[128 * ASTR];
    __shared__ __align__(16) unsigned short Al[128 * ASTR];
    __shared__ __align__(16) unsigned short Bh[128 * ASTR];
    __shared__ __align__(16) unsigned short Bl[128 * ASTR];
    __shared__ float degS[128], b0s[128], b1s[128];

    int tid = threadIdx.x;
    int m0 = blockIdx.x * 128, n0 = blockIdx.y * 128;

    if (tid < 128) {
        int m = m0 + tid;
        if (KVMODE) {
            degS[tid] = (m < M) ? g_deg[m] : 0.f;
            b0s[tid] = g_bc0[n0 + tid];
            b1s[tid] = g_bc1[n0 + tid];
        } else {
            b0s[tid] = qb[tid];
        }
    }
    __syncthreads();

    int lane = tid & 31, wid = tid >> 5;
    int g = lane >> 2, t = lane & 3;
    int wm = (wid >> 2) * 64, wn = (wid & 3) * 32;

    float acc[4][4][4];
    #pragma unroll
    for (int mt = 0; mt < 4; mt++)
        #pragma unroll
        for (int nt = 0; nt < 4; nt++)
            #pragma unroll
            for (int r = 0; r < 4; r++) acc[mt][nt][r] = 0.f;

    int m_r = tid >> 1;
    int khalf = (tid & 1) * 8;

    for (int kt = 0; kt < KDIM / 16; kt++) {
        int kg = kt * 16 + khalf;
        float f[8];
        {
            int m = m0 + m_r;
            if (m < M) {
                const float* src;
                float d = 1.f;
                if (!KVMODE) {
                    src = X + (size_t)m * 128 + kg;
                } else if (kg < 128) {
                    src = X + (size_t)m * 128 + kg;
                    d = degS[m_r];
                } else {
                    src = g_s + (size_t)m * 128 + (kg - 128);
                }
                float4 v0 = *(const float4*)src;
                float4 v1 = *(const float4*)(src + 4);
                f[0] = v0.x * d; f[1] = v0.y * d; f[2] = v0.z * d; f[3] = v0.w * d;
                f[4] = v1.x * d; f[5] = v1.y * d; f[6] = v1.z * d; f[7] = v1.w * d;
            } else {
                #pragma unroll
                for (int j = 0; j < 8; j++) f[j] = 0.f;
            }
        }
        unsigned hi[4], lo[4];
        #pragma unroll
        for (int j = 0; j < 4; j++) {
            __nv_bfloat162 h2 = __floats2bfloat162_rn(f[2 * j], f[2 * j + 1]);
            hi[j] = *(unsigned*)&h2;
            float r0 = f[2 * j]     - __bfloat162float(h2.x);
            float r1 = f[2 * j + 1] - __bfloat162float(h2.y);
            lo[j] = pack_bf2(r0, r1);
        }
        *(uint4*)&Ah[m_r * ASTR + khalf] = make_uint4(hi[0], hi[1], hi[2], hi[3]);
        *(uint4*)&Al[m_r * ASTR + khalf] = make_uint4(lo[0], lo[1], lo[2], lo[3]);
        size_t boff = (size_t)(n0 + m_r) * KDIM + kg;
        *(uint4*)&Bh[m_r * ASTR + khalf] = *(const uint4*)(BHg + boff);
        *(uint4*)&Bl[m_r * ASTR + khalf] = *(const uint4*)(BLg + boff);
        __syncthreads();

        #pragma unroll
        for (int term = 0; term < 3; term++) {
            const unsigned short* As = (term == 2) ? Al : Ah;
            const unsigned short* Bs = (term == 1) ? Bl : Bh;
            unsigned b[4][2];
            #pragma unroll
            for (int nt = 0; nt < 4; nt++) {
                int nb = (wn + nt * 8 + g) * ASTR + 2 * t;
                b[nt][0] = *(const unsigned*)&Bs[nb];
                b[nt][1] = *(const unsigned*)&Bs[nb + 8];
            }
            #pragma unroll
            for (int mt = 0; mt < 4; mt++) {
                int ra = (wm + mt * 16 + g) * ASTR + 2 * t;
                unsigned a0 = *(const unsigned*)&As[ra];
                unsigned a1 = *(const unsigned*)&As[ra + 8 * ASTR];
                unsigned a2 = *(const unsigned*)&As[ra + 8];
                unsigned a3 = *(const unsigned*)&As[ra + 8 * ASTR + 8];
                #pragma unroll
                for (int nt = 0; nt < 4; nt++) {
                    asm volatile(
                        "mma.sync.aligned.m16n8k16.row.col.f32.bf16.bf16.f32 "
                        "{%0,%1,%2,%3}, {%4,%5,%6,%7}, {%8,%9}, {%0,%1,%2,%3};"
                        : "+f"(acc[mt][nt][0]), "+f"(acc[mt][nt][1]),
                          "+f"(acc[mt][nt][2]), "+f"(acc[mt][nt][3])
                        : "r"(a0), "r"(a1), "r"(a2), "r"(a3),
                          "r"(b[nt][0]), "r"(b[nt][1]));
                }
            }
        }
        __syncthreads();
    }

    #pragma unroll
    for (int mt = 0; mt < 4; mt++) {
        int r0l = wm + mt * 16 + g;
        int r1l = r0l + 8;
        int mA = m0 + r0l, mB = m0 + r1l;
        float dA = KVMODE ? degS[r0l] : 0.f;
        float dB = KVMODE ? degS[r1l] : 0.f;
        #pragma unroll
        for (int nt = 0; nt < 4; nt++) {
            int cl = wn + nt * 8 + 2 * t;
            float bia0 = b0s[cl]     + (KVMODE ? dA * b1s[cl]     : 0.f);
            float bia1 = b0s[cl + 1] + (KVMODE ? dA * b1s[cl + 1] : 0.f);
            float bib0 = b0s[cl]     + (KVMODE ? dB * b1s[cl]     : 0.f);
            float bib1 = b0s[cl + 1] + (KVMODE ? dB * b1s[cl + 1] : 0.f);
            if (mA < M) {
                float2 o = make_float2(acc[mt][nt][0] + bia0, acc[mt][nt][1] + bia1);
                *(float2*)(out + (size_t)mA * NLD + n0 + cl) = o;
            }
            if (mB < M) {
                float2 o = make_float2(acc[mt][nt][2] + bib0, acc[mt][nt][3] + bib1);
                *(float2*)(out + (size_t)mB * NLD + n0 + cl) = o;
            }
        }
    }
}

// ---------------- fused attention pass (warp-per-dst, online softmax, 2-edge) ----------------
__global__ void k_attn(int ndst, int E2) {
    __shared__ float wmx[8];
    int warp = (blockIdx.x * blockDim.x + threadIdx.x) >> 5;
    int lane = threadIdx.x & 31;
    int wid = threadIdx.x >> 5;
    float lm = -3.4e38f;
    if (warp < ndst) {
        float4 q = *(const float4*)(g_Q + (size_t)warp * CDIM + lane * 4);
        int b = g_off2[warp], e = g_off2[warp + 1];
        if (b < 0) b = 0;
        if (e > E2) e = E2;
        float Zd = 0.f;
        float4 acc = make_float4(0.f, 0.f, 0.f, 0.f);
        int j = b;
        for (; j + 1 < e; j += 2) {
            unsigned m0 = (unsigned)g_csr2m[j], m1 = (unsigned)g_csr2m[j + 1];
            if (m0 >= NMAX) m0 = 0;
            if (m1 >= NMAX) m1 = 0;
            const float* r0 = g_KV + (size_t)m0 * 2 * CDIM;
            const float* r1 = g_KV + (size_t)m1 * 2 * CDIM;
            float4 k0 = *(const float4*)(r0 + lane * 4);
            float4 k1 = *(const float4*)(r1 + lane * 4);
            float4 v0 = *(const float4*)(r0 + CDIM + lane * 4);
            float4 v1 = *(const float4*)(r1 + CDIM + lane * 4);
            float d0 = k0.x * q.x + k0.y * q.y + k0.z * q.z + k0.w * q.w;
            float d1 = k1.x * q.x + k1.y * q.y + k1.z * q.z + k1.w * q.w;
            #pragma unroll
            for (int o = 16; o > 0; o >>= 1) {
                d0 += __shfl_xor_sync(0xffffffffu, d0, o);
                d1 += __shfl_xor_sync(0xffffffffu, d1, o);
            }
            float s0 = d0 * 0.08838834764831845f;
            float s1 = d1 * 0.08838834764831845f;
            float nm = fmaxf(lm, fmaxf(s0, s1));
            float sc = __expf(lm - nm);
            float w0 = __expf(s0 - nm);
            float w1 = __expf(s1 - nm);
            Zd = Zd * sc + w0 + w1;
            acc.x = acc.x * sc + w0 * v0.x + w1 * v1.x;
            acc.y = acc.y * sc + w0 * v0.y + w1 * v1.y;
            acc.z = acc.z * sc + w0 * v0.z + w1 * v1.z;
            acc.w = acc.w * sc + w0 * v0.w + w1 * v1.w;
            lm = nm;
        }
        if (j < e) {
            unsigned m0 = (unsigned)g_csr2m[j];
            if (m0 >= NMAX) m0 = 0;
            const float* r0 = g_KV + (size_t)m0 * 2 * CDIM;
            float4 k0 = *(const float4*)(r0 + lane * 4);
            float4 v0 = *(const float4*)(r0 + CDIM + lane * 4);
            float d0 = k0.x * q.x + k0.y * q.y + k0.z * q.z + k0.w * q.w;
            #pragma unroll
            for (int o = 16; o > 0; o >>= 1) d0 += __shfl_xor_sync(0xffffffffu, d0, o);
            float s0 = d0 * 0.08838834764831845f;
            float nm = fmaxf(lm, s0);
            float sc = __expf(lm - nm);
            float w0 = __expf(s0 - nm);
            Zd = Zd * sc + w0;
            acc.x = acc.x * sc + w0 * v0.x;
            acc.y = acc.y * sc + w0 * v0.y;
            acc.z = acc.z * sc + w0 * v0.z;
            acc.w = acc.w * sc + w0 * v0.w;
            lm = nm;
        }
        *(float4*)(g_s + (size_t)warp * CDIM + lane * 4) = acc;
        if (lane == 0) { g_lm[warp] = lm; g_Zd[warp] = Zd; }
    }
    if (lane == 0) wmx[wid] = lm;
    __syncthreads();
    if (threadIdx.x == 0) {
        float m = wmx[0];
        #pragma unroll
        for (int r = 1; r < 8; r++) m = fmaxf(m, wmx[r]);
        atomicMax(&g_maxbits, flipf(m));
    }
}

// ---------------- Z = sum_d Zd * exp(lm_d - gm) ----------------
__global__ void k_zZ(int ndst) {
    __shared__ float wm[8];
    float gm = unflipf(g_maxbits);
    float loc = 0.f;
    int i = blockIdx.x * blockDim.x + threadIdx.x;
    int stride = gridDim.x * blockDim.x;
    for (int t = i; t < ndst; t += stride)
        loc += g_Zd[t] * __expf(g_lm[t] - gm);
    #pragma unroll
    for (int o = 16; o > 0; o >>= 1) loc += __shfl_xor_sync(0xffffffffu, loc, o);
    if ((threadIdx.x & 31) == 0) wm[threadIdx.x >> 5] = loc;
    __syncthreads();
    if (threadIdx.x == 0) {
        float bsum = 0.f;
        #pragma unroll
        for (int r = 0; r < 8; r++) bsum += wm[r];
        atomicAdd(&g_Z, bsum);
    }
}

// ---------------- final: out[d] = acc_d * exp(lm_d - gm) / Z ----------------
__global__ void k_final(float* __restrict__ out, int ndst) {
    int i = blockIdx.x * blockDim.x + threadIdx.x;
    int total = ndst * (CDIM / 4);
    if (i >= total) return;
    int d = i >> 5;
    float gm = unflipf(g_maxbits);
    float w = __expf(g_lm[d] - gm) / g_Z;
    float4 a = ((const float4*)g_s)[i];
    float4 o = make_float4(a.x * w, a.y * w, a.z * w, a.w * w);
    ((float4*)out)[i] = o;
}

// ---------------- stream/event pool ----------
namespace {
struct StreamPool {
    cudaStream_t s1 = nullptr, s2 = nullptr;
    cudaEvent_t eS = nullptr, eDZ = nullptr, e1 = nullptr, e2 = nullptr;
    bool ok = false;
    StreamPool() {
        ok = (cudaStreamCreateWithFlags(&s1, cudaStreamNonBlocking) == cudaSuccess) &&
             (cudaStreamCreateWithFlags(&s2, cudaStreamNonBlocking) == cudaSuccess) &&
             (cudaEventCreateWithFlags(&eS,  cudaEventDisableTiming) == cudaSuccess) &&
             (cudaEventCreateWithFlags(&eDZ, cudaEventDisableTiming) == cudaSuccess) &&
             (cudaEventCreateWithFlags(&e1,  cudaEventDisableTiming) == cudaSuccess) &&
             (cudaEventCreateWithFlags(&e2,  cudaEventDisableTiming) == cudaSuccess);
    }
};
StreamPool g_sp;
}

// ---------------- launch ----------------
extern "C" void kernel_launch(void* const* d_in, const int* in_sizes, int n_in,
                              void* d_out, int out_size) {
    const float* x_src = (const float*)d_in[0];
    const float* x_mid = (const float*)d_in[1];
    const float* x_dst = (const float*)d_in[2];
    const void* ei1 = d_in[3];
    const void* ei2 = d_in[4];
    const float* W1w = (const float*)d_in[5];
    const float* W1b = (const float*)d_in[6];
    const float* W2w = (const float*)d_in[7];
    const float* W2b = (const float*)d_in[8];
    const float* qw  = (const float*)d_in[9];
    const float* qb  = (const float*)d_in[10];
    const float* kw  = (const float*)d_in[11];
    const float* kb  = (const float*)d_in[12];
    const float* vw  = (const float*)d_in[13];
    const float* vb  = (const float*)d_in[14];
    float* out = (float*)d_out;

    int E1 = in_sizes[3] / 2;
    int E2 = in_sizes[4] / 2;
    int Nmid = in_sizes[1] / CDIM;
    int Ndst = in_sizes[2] / CDIM;

    dim3 gKV((Nmid + 127) / 128, 2);
    dim3 gQ((Ndst + 127) / 128, 1);
    int foldBlocks = (65536 + 16384 + 256 + 255) / 256;

    if (g_sp.ok) {
        // fork
        cudaEventRecord(g_sp.eS, 0);
        cudaStreamWaitEvent(g_sp.s1, g_sp.eS, 0);

        // track A (s1): detect -> zero -> scatter1 (2 edges/warp)
        k_detect<<<1, 512, 0, g_sp.s1>>>((const int*)ei1);
        k_zero<<<2048, 256, 0, g_sp.s1>>>(Nmid);
        cudaEventRecord(g_sp.eDZ, g_sp.s1);
        k_scatter1<<<(E1 + 15) / 16, 256, 0, g_sp.s1>>>(x_src, ei1, E1);
        cudaEventRecord(g_sp.e1, g_sp.s1);

        // track B (s2): CSR build (needs detect+zero)
        cudaStreamWaitEvent(g_sp.s2, g_sp.eDZ, 0);
        k_count2<<<(E2 + 255) / 256, 256, 0, g_sp.s2>>>(ei2, E2, Nmid);
        k_scan<<<1, 1024, 0, g_sp.s2>>>(Nmid);
        k_fill2<<<(E2 + 255) / 256, 256, 0, g_sp.s2>>>(ei2, E2, Nmid);
        cudaEventRecord(g_sp.e2, g_sp.s2);

        // track C (s0): fold -> Q GEMM (independent of edge work)
        k_fold<<<foldBlocks, 256>>>(W1w, W2w, W1b, W2b, qw, kw, vw, kb, vb);
        k_gemm_tc<false><<<gQ, 256>>>(x_dst, qb, Ndst);

        // join: KV GEMM needs scatter1 (deg, s) + fold (in-order on s0)
        cudaStreamWaitEvent(0, g_sp.e1, 0);
        k_gemm_tc<true><<<gKV, 256>>>(x_mid, nullptr, Nmid);
        // attn needs CSR (e2) + both GEMMs (in-order on s0)
        cudaStreamWaitEvent(0, g_sp.e2, 0);
        k_attn<<<(Ndst + 7) / 8, 256>>>(Ndst, E2);
        k_zZ<<<256, 256>>>(Ndst);
        k_final<<<(Ndst * 32 + 255) / 256, 256>>>(out, Ndst);
    } else {
        // sequential fallback (identical math)
        k_detect<<<1, 512>>>((const int*)ei1);
        k_zero<<<2048, 256>>>(Nmid);
        k_fold<<<foldBlocks, 256>>>(W1w, W2w, W1b, W2b, qw, kw, vw, kb, vb);
        k_scatter1<<<(E1 + 15) / 16, 256>>>(x_src, ei1, E1);
        k_count2<<<(E2 + 255) / 256, 256>>>(ei2, E2, Nmid);
        k_scan<<<1, 1024>>>(Nmid);
        k_fill2<<<(E2 + 255) / 256, 256>>>(ei2, E2, Nmid);
        k_gemm_tc<true><<<gKV, 256>>>(x_mid, nullptr, Nmid);
        k_gemm_tc<false><<<gQ, 256>>>(x_dst, qb, Ndst);
        k_attn<<<(Ndst + 7) / 8, 256>>>(Ndst, E2);
        k_zZ<<<256, 256>>>(Ndst);
        k_final<<<(Ndst * 32 + 255) / 256, 256>>>(out, Ndst);
    }
}